// round 6
// baseline (speedup 1.0000x reference)
#include <cuda_runtime.h>
#include <cstdint>

#define NPROB 512            // B*S = 32*16
#define MDIM  128
#define NDIM  256
#define EPSF  1e-6f
#define MUF   0.01f
#define KITER 30
#define LMAX  25
#define MASK_ALL 0x01FFFFFFu // 25 bits
#define TPB   256
#define CJ    5              // cached row-groups per warp (rows 0..39 in smem)
#define CROWS (CJ * 8)       // 40 rows cached
#define DYNSMEM (CROWS * NDIM * 4)

// Persistent device state
__device__ float    g_Aw[(size_t)NPROB * MDIM * NDIM]; // row-normalized A (64MB)
__device__ unsigned g_and[KITER];                       // global AND of masks per iter
__device__ unsigned g_count;                            // barrier arrival counter
__device__ unsigned g_sense;                            // barrier sense

// NOTE: redux.sync.add.f32 is NOT supported on sm_103 (ptxas rejects it).
// Use the classic 5-stage butterfly; ILP across independent rows hides latency.
__device__ __forceinline__ float warp_allreduce_add(float v) {
#pragma unroll
    for (int o = 16; o; o >>= 1) v += __shfl_xor_sync(0xffffffffu, v, o);
    return v;
}

__device__ __forceinline__ float dot8(float4 a0, float4 a1, float4 b0, float4 b1) {
    float s = a0.x * b0.x + a0.y * b0.y + a0.z * b0.z + a0.w * b0.w;
    s += a1.x * b1.x + a1.y * b1.y + a1.z * b1.z + a1.w * b1.w;
    return s;
}

// Grid-wide sense-reversal barrier. All NPROB CTAs co-resident:
// __launch_bounds__(256,4) + ~54KB smem/CTA -> 4 CTAs/SM * 148 = 592 >= 512.
#define GRID_BARRIER()                                                        \
    do {                                                                      \
        __syncthreads();                                                      \
        if (tid == 0) {                                                       \
            const unsigned target = sense ^ 1u;                               \
            __threadfence();                                                  \
            if (atomicAdd(&g_count, 1u) == NPROB - 1u) {                      \
                atomicExch(&g_count, 0u);                                     \
                __threadfence();                                              \
                atomicExch(&g_sense, target);                                 \
            } else {                                                          \
                while (*(volatile unsigned*)&g_sense != target)               \
                    __nanosleep(32);                                          \
            }                                                                 \
            sense = target;                                                   \
            __threadfence();                                                  \
        }                                                                     \
        __syncthreads();                                                      \
    } while (0)

__global__ void __launch_bounds__(TPB, 4)
persist_kernel(const float* __restrict__ xraw,
               const float* __restrict__ Ain,
               const float* __restrict__ bin,
               const float* __restrict__ lowin,
               float* __restrict__ out)
{
    extern __shared__ __align__(16) float sA[];   // CROWS x NDIM pinned A rows

    const int p    = blockIdx.x;
    const int tid  = threadIdx.x;
    const int lane = tid & 31;
    const int w    = tid >> 5;

    __shared__ __align__(16) float s_x[NDIM];
    __shared__ __align__(16) float s_grad[NDIM];
    __shared__ __align__(16) float s_lo[NDIM];
    __shared__ __align__(16) float s_xr[NDIM];
    __shared__ __align__(16) float s_bw[MDIM];
    __shared__ __align__(16) float s_Ax[MDIM];
    __shared__ __align__(16) float s_gb[8 * NDIM];   // per-warp gbar partials
    __shared__ unsigned s_mask;
    __shared__ float    s_step;
    __shared__ int      s_feas;

    const float* A  = Ain  + (size_t)p * MDIM * NDIM;
    float*       Aw = g_Aw + (size_t)p * MDIM * NDIM;

    // Read sense BEFORE first arrive (all CTAs read pre-flip value).
    unsigned sense = *(volatile unsigned*)&g_sense;

    if (p == 0 && tid < KITER) g_and[tid] = MASK_ALL;

    if (tid < NDIM) {
        s_lo[tid] = lowin[p * NDIM + tid];
        s_xr[tid] = xraw[p * NDIM + tid];
    }
    if (tid == 0) s_feas = 1;
    __syncthreads();

    const int n0 = 4 * lane;
    const int n1 = 128 + 4 * lane;
    const float4 l0 = *(const float4*)(s_lo + n0);
    const float4 l1 = *(const float4*)(s_lo + n1);

    // per-lane line-search step: lane l tests step 2^-l (exact)
    const float stepl = __uint_as_float((unsigned)(127 - lane) << 23);

    float* s_red = s_gb;   // alias: s_gb unused during setup

    // ---------------- setup: row-normalize, cache first 40 rows in smem -----
#pragma unroll 4
    for (int j = 0; j < 16; j++) {
        const int m = w + 8 * j;
        const float4 a0 = *(const float4*)(A + (size_t)m * NDIM + n0);
        const float4 a1 = *(const float4*)(A + (size_t)m * NDIM + n1);
        float ss = warp_allreduce_add(dot8(a0, a1, a0, a1));
        const float norm = fmaxf(sqrtf(ss), 1e-12f);
        float4 w0, w1;
        w0.x = a0.x / norm; w0.y = a0.y / norm; w0.z = a0.z / norm; w0.w = a0.w / norm;
        w1.x = a1.x / norm; w1.y = a1.y / norm; w1.z = a1.z / norm; w1.w = a1.w / norm;
        *(float4*)(Aw + (size_t)m * NDIM + n0) = w0;
        *(float4*)(Aw + (size_t)m * NDIM + n1) = w1;
        if (m < CROWS) {
            *(float4*)(sA + m * NDIM + n0) = w0;
            *(float4*)(sA + m * NDIM + n1) = w1;
        }
        float ad = (w0.x + w0.y + w0.z + w0.w) + (w1.x + w1.y + w1.z + w1.w);
        float sd = dot8(w0, w1, l0, l1);
        ad = warp_allreduce_add(ad);
        sd = warp_allreduce_add(sd);
        if (lane == 0) {
            const float bwm = bin[p * MDIM + m] / norm;
            s_bw[m]  = bwm;
            s_Ax[m]  = ad;          // temp: Ad
            s_red[m] = bwm - sd;    // temp: slack at lower
        }
    }
    __syncthreads();

    // t = max(0.5 * min_m ratio, 2*eps)
    if (tid < MDIM) {
        const float ad = s_Ax[tid];
        s_red[tid] = (ad > 0.f) ? (s_red[tid] / fmaxf(ad, 1e-12f))
                                : __int_as_float(0x7f800000); // +inf
    }
    __syncthreads();
    for (int off = 64; off >= 1; off >>= 1) {
        if (tid < off) s_red[tid] = fminf(s_red[tid], s_red[tid + off]);
        __syncthreads();
    }
    const float t = fmaxf(0.5f * s_red[0], 2.f * EPSF);
    __syncthreads();   // s_red (=s_gb) free again

    // feasibility of x = lower + t (fresh dots)
    {
        float4 xq0, xq1;
        xq0.x = l0.x + t; xq0.y = l0.y + t; xq0.z = l0.z + t; xq0.w = l0.w + t;
        xq1.x = l1.x + t; xq1.y = l1.y + t; xq1.z = l1.z + t; xq1.w = l1.w + t;
#pragma unroll
        for (int j = 0; j < CJ; j++) {
            const int m = w + 8 * j;
            const float4 a0 = *(const float4*)(sA + m * NDIM + n0);
            const float4 a1 = *(const float4*)(sA + m * NDIM + n1);
            float d = warp_allreduce_add(dot8(a0, a1, xq0, xq1));
            if (lane == 0 && !(d <= s_bw[m] - EPSF)) atomicAnd(&s_feas, 0);
        }
#pragma unroll 4
        for (int j = CJ; j < 16; j++) {
            const int m = w + 8 * j;
            const float4 a0 = *(const float4*)(Aw + (size_t)m * NDIM + n0);
            const float4 a1 = *(const float4*)(Aw + (size_t)m * NDIM + n1);
            float d = warp_allreduce_add(dot8(a0, a1, xq0, xq1));
            if (lane == 0 && !(d <= s_bw[m] - EPSF)) atomicAnd(&s_feas, 0);
        }
        if (tid < NDIM) {
            const float xv = s_lo[tid] + t;
            if (!(xv >= s_lo[tid] + EPSF)) atomicAnd(&s_feas, 0);
        }
        __syncthreads();
        if (tid < NDIM) {
            float xv = s_lo[tid] + t;
            if (!s_feas) xv = 0.5f * (fmaxf(xv, 0.f) + s_lo[tid]);
            s_x[tid] = xv;
        }
    }

    GRID_BARRIER();   // barrier #0: g_and init + everyone's setup done

    // ---------------- main loop ---------------------------------------------
    for (int k = 0; k < KITER; k++) {
        if (tid == 0) s_mask = MASK_ALL;
        __syncthreads();

        const float4 xq0 = *(const float4*)(s_x + n0);
        const float4 xq1 = *(const float4*)(s_x + n1);

        float4 ga0 = make_float4(0.f, 0.f, 0.f, 0.f);
        float4 ga1 = make_float4(0.f, 0.f, 0.f, 0.f);

        // pass 1 row body: d = A_m.x ; v = mu/slack ; gbar += A_m * v
#define P1_ROW(a0, a1, m)                                                     \
        do {                                                                  \
            float d = warp_allreduce_add(dot8(a0, a1, xq0, xq1));             \
            const float v = MUF / fmaxf(s_bw[m] - d, 1e-12f);                 \
            if (lane == 0) s_Ax[m] = d;                                       \
            ga0.x = fmaf((a0).x, v, ga0.x); ga0.y = fmaf((a0).y, v, ga0.y);   \
            ga0.z = fmaf((a0).z, v, ga0.z); ga0.w = fmaf((a0).w, v, ga0.w);   \
            ga1.x = fmaf((a1).x, v, ga1.x); ga1.y = fmaf((a1).y, v, ga1.y);   \
            ga1.z = fmaf((a1).z, v, ga1.z); ga1.w = fmaf((a1).w, v, ga1.w);   \
        } while (0)

        // gmem rows ascending (j=CJ..15): j=CJ was read last by prev pass 2
#pragma unroll 4
        for (int j = CJ; j < 16; j++) {
            const int m = w + 8 * j;
            const float4 a0 = *(const float4*)(Aw + (size_t)m * NDIM + n0);
            const float4 a1 = *(const float4*)(Aw + (size_t)m * NDIM + n1);
            P1_ROW(a0, a1, m);
        }
        // smem-pinned rows
#pragma unroll
        for (int j = 0; j < CJ; j++) {
            const int m = w + 8 * j;
            const float4 a0 = *(const float4*)(sA + m * NDIM + n0);
            const float4 a1 = *(const float4*)(sA + m * NDIM + n1);
            P1_ROW(a0, a1, m);
        }
#undef P1_ROW

        *(float4*)(s_gb + w * NDIM + n0) = ga0;
        *(float4*)(s_gb + w * NDIM + n1) = ga1;
        __syncthreads();

        // grad + column-constraint mask bits
        if (tid < NDIM) {
            float gb = 0.f;
#pragma unroll
            for (int j = 0; j < 8; j++) gb += s_gb[j * NDIM + tid];
            const float xv  = s_x[tid];
            const float lov = s_lo[tid];
            const float slo = fmaxf(xv - lov, 1e-12f);
            const float gr  = (xv - s_xr[tid]) + gb + MUF / slo;
            s_grad[tid] = gr;

            const float lim = lov + EPSF;
            if (!(gr <= 0.f && xv >= lim)) {   // fast path: all candidates pass
                unsigned mk = MASK_ALL;
                float st = 1.f;
#pragma unroll
                for (int l = 0; l < LMAX; l++) {
                    const float c = fmaf(-st, gr, xv);
                    if (!(c >= lim)) mk &= ~(1u << l);
                    st *= 0.5f;
                }
                if (mk != MASK_ALL) atomicAnd(&s_mask, mk);
            }
        }
        __syncthreads();

        // pass 2: Ag + row-constraint mask bits via lane-parallel ballot:
        // lane l tests candidate step 2^-l -> bit l. Bit-identical fmaf to
        // the serial loop, branch-free, no 25-iteration ALU chain.
        const float4 gq0 = *(const float4*)(s_grad + n0);
        const float4 gq1 = *(const float4*)(s_grad + n1);
        unsigned wmask = MASK_ALL;

#define P2_ROW(a0, a1, m)                                                     \
        do {                                                                  \
            float ag = warp_allreduce_add(dot8(a0, a1, gq0, gq1));            \
            const float axc = fmaf(-stepl, ag, s_Ax[m]);                      \
            const unsigned bits =                                             \
                __ballot_sync(0xffffffffu, axc <= s_bw[m] - EPSF);            \
            wmask &= (bits | ~MASK_ALL);                                      \
        } while (0)

        // gmem rows DESCENDING (j=15..CJ): j=15 just read by pass 1 -> L1 hot
#pragma unroll 4
        for (int j = 15; j >= CJ; j--) {
            const int m = w + 8 * j;
            const float4 a0 = *(const float4*)(Aw + (size_t)m * NDIM + n0);
            const float4 a1 = *(const float4*)(Aw + (size_t)m * NDIM + n1);
            P2_ROW(a0, a1, m);
        }
        // smem-pinned rows
#pragma unroll
        for (int j = 0; j < CJ; j++) {
            const int m = w + 8 * j;
            const float4 a0 = *(const float4*)(sA + m * NDIM + n0);
            const float4 a1 = *(const float4*)(sA + m * NDIM + n1);
            P2_ROW(a0, a1, m);
        }
#undef P2_ROW

        if (lane == 0 && wmask != MASK_ALL) atomicAnd(&s_mask, wmask);
        __syncthreads();

        if (tid == 0) atomicAnd(&g_and[k], s_mask);

        GRID_BARRIER();   // all masks for iteration k combined

        if (tid == 0) {
            const unsigned tt = *(volatile unsigned*)&g_and[k] & MASK_ALL;
            float st = 0.f;
            if (tt) st = ldexpf(1.f, -(__ffs(tt) - 1));
            s_step = st;
        }
        __syncthreads();

        if (tid < NDIM) s_x[tid] = fmaf(-s_step, s_grad[tid], s_x[tid]);
        // next iteration's leading __syncthreads covers visibility of s_x
    }

    // finalize: relu(x) -> out
    if (tid < NDIM) out[p * NDIM + tid] = fmaxf(s_x[tid], 0.f);
}

extern "C" void kernel_launch(void* const* d_in, const int* in_sizes, int n_in,
                              void* d_out, int out_size) {
    // Identify inputs by size (dict order: x_raw, A, b, lower).
    int iA = 1, ib = 2, iv1 = 0, iv2 = 3;
    {
        int big = -1, small = -1, v1 = -1, v2 = -1;
        for (int i = 0; i < n_in; i++) {
            if (in_sizes[i] == NPROB * MDIM * NDIM) big = i;
            else if (in_sizes[i] == NPROB * MDIM)   small = i;
            else if (v1 < 0) v1 = i;
            else             v2 = i;
        }
        if (big >= 0 && small >= 0 && v1 >= 0 && v2 >= 0) {
            iA = big; ib = small; iv1 = v1; iv2 = v2;
        }
    }
    const float* xr  = (const float*)d_in[iv1];
    const float* A   = (const float*)d_in[iA];
    const float* b   = (const float*)d_in[ib];
    const float* low = (const float*)d_in[iv2];
    float* out = (float*)d_out;

    // Opt-in: static (~13.4KB) + dynamic (40KB) > 48KB default per-block limit.
    // Not a stream-ordered call -> does not enter / invalidate graph capture.
    cudaFuncSetAttribute(persist_kernel,
                         cudaFuncAttributeMaxDynamicSharedMemorySize, DYNSMEM);

    persist_kernel<<<NPROB, TPB, DYNSMEM>>>(xr, A, b, low, out);
}

// round 7
// speedup vs baseline: 1.5722x; 1.5722x over previous
#include <cuda_runtime.h>
#include <cstdint>

#define NPROB 512            // B*S = 32*16
#define MDIM  128
#define NDIM  256
#define EPSF  1e-6f
#define MUF   0.01f
#define KITER 30
#define LMAX  25
#define MASK_ALL 0x01FFFFFFu // 25 bits
#define TPB   256
#define CJ    5              // cached row-groups per warp (rows 0..39 in smem)
#define CROWS (CJ * 8)       // 40 rows cached
#define DYNSMEM (CROWS * NDIM * 4)

typedef unsigned long long u64;

// Persistent device state
__device__ float    g_Aw[(size_t)NPROB * MDIM * NDIM]; // row-normalized A (64MB)
__device__ unsigned g_and[KITER];                       // global AND of masks per iter
__device__ unsigned g_count;                            // barrier arrival counter
__device__ unsigned g_sense;                            // barrier sense

// ---- packed f32x2 helpers (sm_103a FFMA2 path; per-element IEEE fp32) ----
__device__ __forceinline__ u64 pack2(float x, float y) {
    u64 r; asm("mov.b64 %0, {%1, %2};" : "=l"(r) : "f"(x), "f"(y)); return r;
}
__device__ __forceinline__ void unpack2(u64 v, float& x, float& y) {
    asm("mov.b64 {%0, %1}, %2;" : "=f"(x), "=f"(y) : "l"(v));
}
__device__ __forceinline__ u64 fma2(u64 a, u64 b, u64 c) {
    u64 d; asm("fma.rn.f32x2 %0, %1, %2, %3;" : "=l"(d) : "l"(a), "l"(b), "l"(c));
    return d;
}
__device__ __forceinline__ u64 mul2(u64 a, u64 b) {
    u64 d; asm("mul.rn.f32x2 %0, %1, %2;" : "=l"(d) : "l"(a), "l"(b));
    return d;
}

// NOTE: redux.sync.add.f32 is NOT supported on sm_103 (ptxas rejects it).
__device__ __forceinline__ float warp_allreduce_add(float v) {
#pragma unroll
    for (int o = 16; o; o >>= 1) v += __shfl_xor_sync(0xffffffffu, v, o);
    return v;
}

__device__ __forceinline__ float dot8(float4 a0, float4 a1, float4 b0, float4 b1) {
    float s = a0.x * b0.x + a0.y * b0.y + a0.z * b0.z + a0.w * b0.w;
    s += a1.x * b1.x + a1.y * b1.y + a1.z * b1.z + a1.w * b1.w;
    return s;
}

// Grid-wide sense-reversal barrier. All NPROB CTAs co-resident:
// __launch_bounds__(256,4) + ~54KB smem/CTA -> 4 CTAs/SM * 148 = 592 >= 512.
#define GRID_BARRIER()                                                        \
    do {                                                                      \
        __syncthreads();                                                      \
        if (tid == 0) {                                                       \
            const unsigned target = sense ^ 1u;                               \
            __threadfence();                                                  \
            if (atomicAdd(&g_count, 1u) == NPROB - 1u) {                      \
                atomicExch(&g_count, 0u);                                     \
                __threadfence();                                              \
                atomicExch(&g_sense, target);                                 \
            } else {                                                          \
                while (*(volatile unsigned*)&g_sense != target)               \
                    __nanosleep(64);                                          \
            }                                                                 \
            sense = target;                                                   \
            __threadfence();                                                  \
        }                                                                     \
        __syncthreads();                                                      \
    } while (0)

__global__ void __launch_bounds__(TPB, 4)
persist_kernel(const float* __restrict__ xraw,
               const float* __restrict__ Ain,
               const float* __restrict__ bin,
               const float* __restrict__ lowin,
               float* __restrict__ out)
{
    extern __shared__ __align__(16) float sA[];   // CROWS x NDIM pinned A rows

    const int p    = blockIdx.x;
    const int tid  = threadIdx.x;
    const int lane = tid & 31;
    const int w    = tid >> 5;

    __shared__ __align__(16) float s_x[NDIM];
    __shared__ __align__(16) float s_grad[NDIM];
    __shared__ __align__(16) float s_lo[NDIM];
    __shared__ __align__(16) float s_xr[NDIM];
    __shared__ __align__(16) float s_bw[MDIM];
    __shared__ __align__(16) float s_Ax[MDIM];
    __shared__ __align__(16) float s_gb[8 * NDIM];   // per-warp gbar partials
    __shared__ unsigned s_mask;
    __shared__ float    s_step;
    __shared__ int      s_feas;

    const float* A  = Ain  + (size_t)p * MDIM * NDIM;
    float*       Aw = g_Aw + (size_t)p * MDIM * NDIM;

    // Read sense BEFORE first arrive (all CTAs read pre-flip value).
    unsigned sense = *(volatile unsigned*)&g_sense;

    if (p == 0 && tid < KITER) g_and[tid] = MASK_ALL;

    if (tid < NDIM) {
        s_lo[tid] = lowin[p * NDIM + tid];
        s_xr[tid] = xraw[p * NDIM + tid];
    }
    if (tid == 0) s_feas = 1;
    __syncthreads();

    const int n0 = 4 * lane;
    const int n1 = 128 + 4 * lane;
    const float4 l0 = *(const float4*)(s_lo + n0);
    const float4 l1 = *(const float4*)(s_lo + n1);

    float* s_red = s_gb;   // alias: s_gb unused during setup

    // ---------------- setup: row-normalize, cache first 40 rows in smem -----
    // (runs once; keep exact IEEE div here)
#pragma unroll 4
    for (int j = 0; j < 16; j++) {
        const int m = w + 8 * j;
        const float4 a0 = *(const float4*)(A + (size_t)m * NDIM + n0);
        const float4 a1 = *(const float4*)(A + (size_t)m * NDIM + n1);
        float ss = warp_allreduce_add(dot8(a0, a1, a0, a1));
        const float norm = fmaxf(sqrtf(ss), 1e-12f);
        float4 w0, w1;
        w0.x = a0.x / norm; w0.y = a0.y / norm; w0.z = a0.z / norm; w0.w = a0.w / norm;
        w1.x = a1.x / norm; w1.y = a1.y / norm; w1.z = a1.z / norm; w1.w = a1.w / norm;
        *(float4*)(Aw + (size_t)m * NDIM + n0) = w0;
        *(float4*)(Aw + (size_t)m * NDIM + n1) = w1;
        if (m < CROWS) {
            *(float4*)(sA + m * NDIM + n0) = w0;
            *(float4*)(sA + m * NDIM + n1) = w1;
        }
        float ad = (w0.x + w0.y + w0.z + w0.w) + (w1.x + w1.y + w1.z + w1.w);
        float sd = dot8(w0, w1, l0, l1);
        ad = warp_allreduce_add(ad);
        sd = warp_allreduce_add(sd);
        if (lane == 0) {
            const float bwm = bin[p * MDIM + m] / norm;
            s_bw[m]  = bwm;
            s_Ax[m]  = ad;          // temp: Ad
            s_red[m] = bwm - sd;    // temp: slack at lower
        }
    }
    __syncthreads();

    // t = max(0.5 * min_m ratio, 2*eps)
    if (tid < MDIM) {
        const float ad = s_Ax[tid];
        s_red[tid] = (ad > 0.f) ? (s_red[tid] / fmaxf(ad, 1e-12f))
                                : __int_as_float(0x7f800000); // +inf
    }
    __syncthreads();
    for (int off = 64; off >= 1; off >>= 1) {
        if (tid < off) s_red[tid] = fminf(s_red[tid], s_red[tid + off]);
        __syncthreads();
    }
    const float t = fmaxf(0.5f * s_red[0], 2.f * EPSF);
    __syncthreads();   // s_red (=s_gb) free again

    // feasibility of x = lower + t (fresh dots)
    {
        float4 xq0, xq1;
        xq0.x = l0.x + t; xq0.y = l0.y + t; xq0.z = l0.z + t; xq0.w = l0.w + t;
        xq1.x = l1.x + t; xq1.y = l1.y + t; xq1.z = l1.z + t; xq1.w = l1.w + t;
#pragma unroll
        for (int j = 0; j < CJ; j++) {
            const int m = w + 8 * j;
            const float4 a0 = *(const float4*)(sA + m * NDIM + n0);
            const float4 a1 = *(const float4*)(sA + m * NDIM + n1);
            float d = warp_allreduce_add(dot8(a0, a1, xq0, xq1));
            if (lane == 0 && !(d <= s_bw[m] - EPSF)) atomicAnd(&s_feas, 0);
        }
#pragma unroll 4
        for (int j = CJ; j < 16; j++) {
            const int m = w + 8 * j;
            const float4 a0 = *(const float4*)(Aw + (size_t)m * NDIM + n0);
            const float4 a1 = *(const float4*)(Aw + (size_t)m * NDIM + n1);
            float d = warp_allreduce_add(dot8(a0, a1, xq0, xq1));
            if (lane == 0 && !(d <= s_bw[m] - EPSF)) atomicAnd(&s_feas, 0);
        }
        if (tid < NDIM) {
            const float xv = s_lo[tid] + t;
            if (!(xv >= s_lo[tid] + EPSF)) atomicAnd(&s_feas, 0);
        }
        __syncthreads();
        if (tid < NDIM) {
            float xv = s_lo[tid] + t;
            if (!s_feas) xv = 0.5f * (fmaxf(xv, 0.f) + s_lo[tid]);
            s_x[tid] = xv;
        }
    }

    GRID_BARRIER();   // barrier #0: g_and init + everyone's setup done

    // ---------------- main loop ---------------------------------------------
    for (int k = 0; k < KITER; k++) {
        if (tid == 0) s_mask = MASK_ALL;
        __syncthreads();

        // packed x for this iteration (2 fp32 per u64)
        const ulonglong2 xA = *(const ulonglong2*)(s_x + n0);
        const ulonglong2 xB = *(const ulonglong2*)(s_x + n1);

        u64 ga0 = 0ull, ga1 = 0ull, ga2 = 0ull, ga3 = 0ull;  // (0f,0f) packed

        // pass 1 row body: d = A_m.x ; v = mu/slack ; gbar += A_m * v
#define P1_ROW(A0, A1, m)                                                     \
        do {                                                                  \
            u64 s = mul2((A0).x, xA.x);                                       \
            s = fma2((A0).y, xA.y, s);                                        \
            s = fma2((A1).x, xB.x, s);                                        \
            s = fma2((A1).y, xB.y, s);                                        \
            float slo_, shi_; unpack2(s, slo_, shi_);                         \
            float d = warp_allreduce_add(slo_ + shi_);                        \
            const float v = __fdividef(MUF, fmaxf(s_bw[m] - d, 1e-12f));      \
            if (lane == 0) s_Ax[m] = d;                                       \
            const u64 vv = pack2(v, v);                                       \
            ga0 = fma2((A0).x, vv, ga0); ga1 = fma2((A0).y, vv, ga1);         \
            ga2 = fma2((A1).x, vv, ga2); ga3 = fma2((A1).y, vv, ga3);         \
        } while (0)

        // gmem rows ascending (j=CJ..15): j=CJ was read last by prev pass 2
#pragma unroll 4
        for (int j = CJ; j < 16; j++) {
            const int m = w + 8 * j;
            const ulonglong2 a0 = *(const ulonglong2*)(Aw + (size_t)m * NDIM + n0);
            const ulonglong2 a1 = *(const ulonglong2*)(Aw + (size_t)m * NDIM + n1);
            P1_ROW(a0, a1, m);
        }
        // smem-pinned rows
#pragma unroll
        for (int j = 0; j < CJ; j++) {
            const int m = w + 8 * j;
            const ulonglong2 a0 = *(const ulonglong2*)(sA + m * NDIM + n0);
            const ulonglong2 a1 = *(const ulonglong2*)(sA + m * NDIM + n1);
            P1_ROW(a0, a1, m);
        }
#undef P1_ROW

        {
            ulonglong2 t0; t0.x = ga0; t0.y = ga1;
            ulonglong2 t1; t1.x = ga2; t1.y = ga3;
            *(ulonglong2*)(s_gb + w * NDIM + n0) = t0;
            *(ulonglong2*)(s_gb + w * NDIM + n1) = t1;
        }
        __syncthreads();

        // grad + column-constraint mask bits
        if (tid < NDIM) {
            float gb = 0.f;
#pragma unroll
            for (int j = 0; j < 8; j++) gb += s_gb[j * NDIM + tid];
            const float xv  = s_x[tid];
            const float lov = s_lo[tid];
            const float slo = fmaxf(xv - lov, 1e-12f);
            const float gr  = (xv - s_xr[tid]) + gb + __fdividef(MUF, slo);
            s_grad[tid] = gr;

            const float lim = lov + EPSF;
            if (!(gr <= 0.f && xv >= lim)) {   // fast path: all candidates pass
                unsigned mk = MASK_ALL;
                float st = 1.f;
#pragma unroll
                for (int l = 0; l < LMAX; l++) {
                    const float c = fmaf(-st, gr, xv);
                    if (!(c >= lim)) mk &= ~(1u << l);
                    st *= 0.5f;
                }
                if (mk != MASK_ALL) atomicAnd(&s_mask, mk);
            }
        }
        __syncthreads();

        // pass 2: Ag + row-constraint mask bits (serial search + fast path)
        const ulonglong2 gA = *(const ulonglong2*)(s_grad + n0);
        const ulonglong2 gB = *(const ulonglong2*)(s_grad + n1);
        unsigned wmask = MASK_ALL;

#define P2_ROW(A0, A1, m)                                                     \
        do {                                                                  \
            u64 s = mul2((A0).x, gA.x);                                       \
            s = fma2((A0).y, gA.y, s);                                        \
            s = fma2((A1).x, gB.x, s);                                        \
            s = fma2((A1).y, gB.y, s);                                        \
            float slo_, shi_; unpack2(s, slo_, shi_);                         \
            float ag = warp_allreduce_add(slo_ + shi_);                       \
            const float ax  = s_Ax[m];                                        \
            const float lim = s_bw[m] - EPSF;                                 \
            if (!(ag >= 0.f && ax <= lim)) {                                  \
                float st = 1.f;                                               \
                _Pragma("unroll")                                             \
                for (int l = 0; l < LMAX; l++) {                              \
                    const float axc = fmaf(-st, ag, ax);                      \
                    if (!(axc <= lim)) wmask &= ~(1u << l);                   \
                    st *= 0.5f;                                               \
                }                                                             \
            }                                                                 \
        } while (0)

        // gmem rows DESCENDING (j=15..CJ): j=15 just read by pass 1 -> L1 hot
#pragma unroll 4
        for (int j = 15; j >= CJ; j--) {
            const int m = w + 8 * j;
            const ulonglong2 a0 = *(const ulonglong2*)(Aw + (size_t)m * NDIM + n0);
            const ulonglong2 a1 = *(const ulonglong2*)(Aw + (size_t)m * NDIM + n1);
            P2_ROW(a0, a1, m);
        }
        // smem-pinned rows
#pragma unroll
        for (int j = 0; j < CJ; j++) {
            const int m = w + 8 * j;
            const ulonglong2 a0 = *(const ulonglong2*)(sA + m * NDIM + n0);
            const ulonglong2 a1 = *(const ulonglong2*)(sA + m * NDIM + n1);
            P2_ROW(a0, a1, m);
        }
#undef P2_ROW

        if (lane == 0 && wmask != MASK_ALL) atomicAnd(&s_mask, wmask);
        __syncthreads();

        if (tid == 0) atomicAnd(&g_and[k], s_mask);

        GRID_BARRIER();   // all masks for iteration k combined

        if (tid == 0) {
            const unsigned tt = *(volatile unsigned*)&g_and[k] & MASK_ALL;
            float st = 0.f;
            if (tt) st = ldexpf(1.f, -(__ffs(tt) - 1));
            s_step = st;
        }
        __syncthreads();

        if (tid < NDIM) s_x[tid] = fmaf(-s_step, s_grad[tid], s_x[tid]);
        // next iteration's leading __syncthreads covers visibility of s_x
    }

    // finalize: relu(x) -> out
    if (tid < NDIM) out[p * NDIM + tid] = fmaxf(s_x[tid], 0.f);
}

extern "C" void kernel_launch(void* const* d_in, const int* in_sizes, int n_in,
                              void* d_out, int out_size) {
    // Identify inputs by size (dict order: x_raw, A, b, lower).
    int iA = 1, ib = 2, iv1 = 0, iv2 = 3;
    {
        int big = -1, small = -1, v1 = -1, v2 = -1;
        for (int i = 0; i < n_in; i++) {
            if (in_sizes[i] == NPROB * MDIM * NDIM) big = i;
            else if (in_sizes[i] == NPROB * MDIM)   small = i;
            else if (v1 < 0) v1 = i;
            else             v2 = i;
        }
        if (big >= 0 && small >= 0 && v1 >= 0 && v2 >= 0) {
            iA = big; ib = small; iv1 = v1; iv2 = v2;
        }
    }
    const float* xr  = (const float*)d_in[iv1];
    const float* A   = (const float*)d_in[iA];
    const float* b   = (const float*)d_in[ib];
    const float* low = (const float*)d_in[iv2];
    float* out = (float*)d_out;

    // Opt-in: static (~13.4KB) + dynamic (40KB) > 48KB default per-block limit.
    // Not a stream-ordered call -> does not enter / invalidate graph capture.
    cudaFuncSetAttribute(persist_kernel,
                         cudaFuncAttributeMaxDynamicSharedMemorySize, DYNSMEM);

    persist_kernel<<<NPROB, TPB, DYNSMEM>>>(xr, A, b, low, out);
}

// round 8
// speedup vs baseline: 1.7401x; 1.1068x over previous
#include <cuda_runtime.h>
#include <cstdint>

#define NPROB 512            // B*S = 32*16
#define MDIM  128
#define NDIM  256
#define EPSF  1e-6f
#define MUF   0.01f
#define KITER 30
#define LMAX  25
#define MASK_ALL 0x01FFFFFFu // 25 bits
#define TPB   256
#define CJ    5              // cached row-groups per warp (rows 0..39 in smem)
#define CROWS (CJ * 8)       // 40 rows cached
#define DYNSMEM (CROWS * NDIM * 4)

typedef unsigned long long u64;

// Persistent device state
__device__ float    g_Aw[(size_t)NPROB * MDIM * NDIM]; // row-normalized A (64MB)
__device__ unsigned g_and[KITER];                       // global AND of masks per iter
__device__ unsigned g_count;                            // barrier arrival counter
__device__ unsigned g_sense;                            // barrier sense

// ---- packed f32x2 helpers (sm_103a FFMA2 path; per-element IEEE fp32) ----
__device__ __forceinline__ u64 pack2(float x, float y) {
    u64 r; asm("mov.b64 %0, {%1, %2};" : "=l"(r) : "f"(x), "f"(y)); return r;
}
__device__ __forceinline__ void unpack2(u64 v, float& x, float& y) {
    asm("mov.b64 {%0, %1}, %2;" : "=f"(x), "=f"(y) : "l"(v));
}
__device__ __forceinline__ u64 fma2(u64 a, u64 b, u64 c) {
    u64 d; asm("fma.rn.f32x2 %0, %1, %2, %3;" : "=l"(d) : "l"(a), "l"(b), "l"(c));
    return d;
}
__device__ __forceinline__ u64 mul2(u64 a, u64 b) {
    u64 d; asm("mul.rn.f32x2 %0, %1, %2;" : "=l"(d) : "l"(a), "l"(b));
    return d;
}

// NOTE: redux.sync.add.f32 is NOT supported on sm_103 (ptxas rejects it).
__device__ __forceinline__ float warp_allreduce_add(float v) {
#pragma unroll
    for (int o = 16; o; o >>= 1) v += __shfl_xor_sync(0xffffffffu, v, o);
    return v;
}

__device__ __forceinline__ float dot8(float4 a0, float4 a1, float4 b0, float4 b1) {
    float s = a0.x * b0.x + a0.y * b0.y + a0.z * b0.z + a0.w * b0.w;
    s += a1.x * b1.x + a1.y * b1.y + a1.z * b1.z + a1.w * b1.w;
    return s;
}

// Grid-wide sense-reversal barrier. All NPROB CTAs co-resident:
// __launch_bounds__(256,4) + ~55KB smem/CTA -> 4 CTAs/SM * 148 = 592 >= 512.
#define GRID_BARRIER()                                                        \
    do {                                                                      \
        __syncthreads();                                                      \
        if (tid == 0) {                                                       \
            const unsigned target = sense ^ 1u;                               \
            __threadfence();                                                  \
            if (atomicAdd(&g_count, 1u) == NPROB - 1u) {                      \
                atomicExch(&g_count, 0u);                                     \
                __threadfence();                                              \
                atomicExch(&g_sense, target);                                 \
            } else {                                                          \
                while (*(volatile unsigned*)&g_sense != target)               \
                    __nanosleep(64);                                          \
            }                                                                 \
            sense = target;                                                   \
            __threadfence();                                                  \
        }                                                                     \
        __syncthreads();                                                      \
    } while (0)

__global__ void __launch_bounds__(TPB, 4)
persist_kernel(const float* __restrict__ xraw,
               const float* __restrict__ Ain,
               const float* __restrict__ bin,
               const float* __restrict__ lowin,
               float* __restrict__ out)
{
    extern __shared__ __align__(16) float sA[];   // CROWS x NDIM pinned A rows

    const int p    = blockIdx.x;
    const int tid  = threadIdx.x;
    const int lane = tid & 31;
    const int w    = tid >> 5;

    __shared__ __align__(16) float s_x[NDIM];
    __shared__ __align__(16) float s_grad[NDIM];
    __shared__ __align__(16) float s_lo[NDIM];
    __shared__ __align__(16) float s_xr[NDIM];
    __shared__ __align__(16) float s_bw[MDIM];
    __shared__ __align__(16) float s_Ax[MDIM];
    __shared__ __align__(16) float s_Ag[MDIM];
    __shared__ __align__(16) float s_v[MDIM];
    __shared__ __align__(16) float s_gb[8 * NDIM];   // per-warp gbar partials
    __shared__ unsigned s_mask;
    __shared__ float    s_step;
    __shared__ int      s_feas;

    const float* A  = Ain  + (size_t)p * MDIM * NDIM;
    float*       Aw = g_Aw + (size_t)p * MDIM * NDIM;

    // Read sense BEFORE first arrive (all CTAs read pre-flip value).
    unsigned sense = *(volatile unsigned*)&g_sense;

    if (p == 0 && tid < KITER) g_and[tid] = MASK_ALL;

    if (tid < NDIM) {
        s_lo[tid] = lowin[p * NDIM + tid];
        s_xr[tid] = xraw[p * NDIM + tid];
    }
    if (tid == 0) s_feas = 1;
    __syncthreads();

    const int n0 = 4 * lane;
    const int n1 = 128 + 4 * lane;
    const float4 l0 = *(const float4*)(s_lo + n0);
    const float4 l1 = *(const float4*)(s_lo + n1);

    float* s_red = s_gb;   // alias: s_gb unused during setup

    // ---------------- setup: row-normalize, cache first 40 rows in smem -----
#pragma unroll 4
    for (int j = 0; j < 16; j++) {
        const int m = w + 8 * j;
        const float4 a0 = *(const float4*)(A + (size_t)m * NDIM + n0);
        const float4 a1 = *(const float4*)(A + (size_t)m * NDIM + n1);
        float ss = warp_allreduce_add(dot8(a0, a1, a0, a1));
        const float norm = fmaxf(sqrtf(ss), 1e-12f);
        float4 w0, w1;
        w0.x = a0.x / norm; w0.y = a0.y / norm; w0.z = a0.z / norm; w0.w = a0.w / norm;
        w1.x = a1.x / norm; w1.y = a1.y / norm; w1.z = a1.z / norm; w1.w = a1.w / norm;
        *(float4*)(Aw + (size_t)m * NDIM + n0) = w0;
        *(float4*)(Aw + (size_t)m * NDIM + n1) = w1;
        if (m < CROWS) {
            *(float4*)(sA + m * NDIM + n0) = w0;
            *(float4*)(sA + m * NDIM + n1) = w1;
        }
        float ad = (w0.x + w0.y + w0.z + w0.w) + (w1.x + w1.y + w1.z + w1.w);
        float sd = dot8(w0, w1, l0, l1);
        ad = warp_allreduce_add(ad);
        sd = warp_allreduce_add(sd);
        if (lane == 0) {
            const float bwm = bin[p * MDIM + m] / norm;
            s_bw[m]  = bwm;
            s_Ax[m]  = ad;          // temp: Ad
            s_red[m] = bwm - sd;    // temp: slack at lower
        }
    }
    __syncthreads();

    // t = max(0.5 * min_m ratio, 2*eps)
    if (tid < MDIM) {
        const float ad = s_Ax[tid];
        s_red[tid] = (ad > 0.f) ? (s_red[tid] / fmaxf(ad, 1e-12f))
                                : __int_as_float(0x7f800000); // +inf
    }
    __syncthreads();
    for (int off = 64; off >= 1; off >>= 1) {
        if (tid < off) s_red[tid] = fminf(s_red[tid], s_red[tid + off]);
        __syncthreads();
    }
    const float t = fmaxf(0.5f * s_red[0], 2.f * EPSF);
    __syncthreads();   // s_red (=s_gb) free again

    // feasibility of x = lower + t (fresh dots); also seeds s_Ax = A*x
    {
        float4 xq0, xq1;
        xq0.x = l0.x + t; xq0.y = l0.y + t; xq0.z = l0.z + t; xq0.w = l0.w + t;
        xq1.x = l1.x + t; xq1.y = l1.y + t; xq1.z = l1.z + t; xq1.w = l1.w + t;
#pragma unroll
        for (int j = 0; j < CJ; j++) {
            const int m = w + 8 * j;
            const float4 a0 = *(const float4*)(sA + m * NDIM + n0);
            const float4 a1 = *(const float4*)(sA + m * NDIM + n1);
            float d = warp_allreduce_add(dot8(a0, a1, xq0, xq1));
            if (lane == 0) {
                s_Ax[m] = d;
                if (!(d <= s_bw[m] - EPSF)) atomicAnd(&s_feas, 0);
            }
        }
#pragma unroll 4
        for (int j = CJ; j < 16; j++) {
            const int m = w + 8 * j;
            const float4 a0 = *(const float4*)(Aw + (size_t)m * NDIM + n0);
            const float4 a1 = *(const float4*)(Aw + (size_t)m * NDIM + n1);
            float d = warp_allreduce_add(dot8(a0, a1, xq0, xq1));
            if (lane == 0) {
                s_Ax[m] = d;
                if (!(d <= s_bw[m] - EPSF)) atomicAnd(&s_feas, 0);
            }
        }
        if (tid < NDIM) {
            const float xv = s_lo[tid] + t;
            if (!(xv >= s_lo[tid] + EPSF)) atomicAnd(&s_feas, 0);
        }
        __syncthreads();
        if (tid < NDIM) {
            float xv = s_lo[tid] + t;
            if (!s_feas) xv = 0.5f * (fmaxf(xv, 0.f) + s_lo[tid]);
            s_x[tid] = xv;
        }
        __syncthreads();
        if (!s_feas) {   // rare repair branch: recompute Ax of repaired x
            const float4 r0 = *(const float4*)(s_x + n0);
            const float4 r1 = *(const float4*)(s_x + n1);
            for (int j = 0; j < 16; j++) {
                const int m = w + 8 * j;
                const float* src = (j < CJ) ? (sA + m * NDIM)
                                            : (Aw + (size_t)m * NDIM);
                const float4 a0 = *(const float4*)(src + n0);
                const float4 a1 = *(const float4*)(src + n1);
                float d = warp_allreduce_add(dot8(a0, a1, r0, r1));
                if (lane == 0) s_Ax[m] = d;
            }
        }
    }

    GRID_BARRIER();   // barrier #0: g_and init + everyone's setup done

    // ---------------- main loop (incremental Ax: Ax_{k+1} = Ax_k - step*Ag) --
    for (int k = 0; k < KITER; k++) {
        if (tid == 0) s_mask = MASK_ALL;
        // v[m] = mu / max(bw - Ax, 1e-12) -- Ax maintained incrementally
        if (tid < MDIM)
            s_v[tid] = __fdividef(MUF, fmaxf(s_bw[tid] - s_Ax[tid], 1e-12f));
        __syncthreads();

        // ---- pass G: gbar partials (pure streaming, no reduce/div) ---------
        u64 ga0 = 0ull, ga1 = 0ull, ga2 = 0ull, ga3 = 0ull;

#define PG_ROW(A0, A1, m)                                                     \
        do {                                                                  \
            const float v_ = s_v[m];                                          \
            const u64 vv = pack2(v_, v_);                                     \
            ga0 = fma2((A0).x, vv, ga0); ga1 = fma2((A0).y, vv, ga1);         \
            ga2 = fma2((A1).x, vv, ga2); ga3 = fma2((A1).y, vv, ga3);         \
        } while (0)

        // gmem rows ascending (j=CJ..15)
#pragma unroll 4
        for (int j = CJ; j < 16; j++) {
            const int m = w + 8 * j;
            const ulonglong2 a0 = *(const ulonglong2*)(Aw + (size_t)m * NDIM + n0);
            const ulonglong2 a1 = *(const ulonglong2*)(Aw + (size_t)m * NDIM + n1);
            PG_ROW(a0, a1, m);
        }
        // smem-pinned rows
#pragma unroll
        for (int j = 0; j < CJ; j++) {
            const int m = w + 8 * j;
            const ulonglong2 a0 = *(const ulonglong2*)(sA + m * NDIM + n0);
            const ulonglong2 a1 = *(const ulonglong2*)(sA + m * NDIM + n1);
            PG_ROW(a0, a1, m);
        }
#undef PG_ROW

        {
            ulonglong2 t0; t0.x = ga0; t0.y = ga1;
            ulonglong2 t1; t1.x = ga2; t1.y = ga3;
            *(ulonglong2*)(s_gb + w * NDIM + n0) = t0;
            *(ulonglong2*)(s_gb + w * NDIM + n1) = t1;
        }
        __syncthreads();

        // grad + column-constraint mask bits
        if (tid < NDIM) {
            float gb = 0.f;
#pragma unroll
            for (int j = 0; j < 8; j++) gb += s_gb[j * NDIM + tid];
            const float xv  = s_x[tid];
            const float lov = s_lo[tid];
            const float slo = fmaxf(xv - lov, 1e-12f);
            const float gr  = (xv - s_xr[tid]) + gb + __fdividef(MUF, slo);
            s_grad[tid] = gr;

            const float lim = lov + EPSF;
            if (!(gr <= 0.f && xv >= lim)) {   // fast path: all candidates pass
                unsigned mk = MASK_ALL;
                float st = 1.f;
#pragma unroll
                for (int l = 0; l < LMAX; l++) {
                    const float c = fmaf(-st, gr, xv);
                    if (!(c >= lim)) mk &= ~(1u << l);
                    st *= 0.5f;
                }
                if (mk != MASK_ALL) atomicAnd(&s_mask, mk);
            }
        }
        __syncthreads();

        // ---- pass A: Ag dots + row-constraint mask bits ---------------------
        const ulonglong2 gA = *(const ulonglong2*)(s_grad + n0);
        const ulonglong2 gB = *(const ulonglong2*)(s_grad + n1);
        unsigned wmask = MASK_ALL;

#define PA_ROW(A0, A1, m)                                                     \
        do {                                                                  \
            u64 s = mul2((A0).x, gA.x);                                       \
            s = fma2((A0).y, gA.y, s);                                        \
            s = fma2((A1).x, gB.x, s);                                        \
            s = fma2((A1).y, gB.y, s);                                        \
            float slo_, shi_; unpack2(s, slo_, shi_);                         \
            float ag = warp_allreduce_add(slo_ + shi_);                       \
            if (lane == 0) s_Ag[m] = ag;                                      \
            const float ax  = s_Ax[m];                                        \
            const float lim = s_bw[m] - EPSF;                                 \
            if (!(ag >= 0.f && ax <= lim)) {                                  \
                float st = 1.f;                                               \
                _Pragma("unroll")                                             \
                for (int l = 0; l < LMAX; l++) {                              \
                    const float axc = fmaf(-st, ag, ax);                      \
                    if (!(axc <= lim)) wmask &= ~(1u << l);                   \
                    st *= 0.5f;                                               \
                }                                                             \
            }                                                                 \
        } while (0)

        // gmem rows DESCENDING (j=15..CJ): j=15 just read by pass G -> L1 hot
#pragma unroll 4
        for (int j = 15; j >= CJ; j--) {
            const int m = w + 8 * j;
            const ulonglong2 a0 = *(const ulonglong2*)(Aw + (size_t)m * NDIM + n0);
            const ulonglong2 a1 = *(const ulonglong2*)(Aw + (size_t)m * NDIM + n1);
            PA_ROW(a0, a1, m);
        }
        // smem-pinned rows
#pragma unroll
        for (int j = 0; j < CJ; j++) {
            const int m = w + 8 * j;
            const ulonglong2 a0 = *(const ulonglong2*)(sA + m * NDIM + n0);
            const ulonglong2 a1 = *(const ulonglong2*)(sA + m * NDIM + n1);
            PA_ROW(a0, a1, m);
        }
#undef PA_ROW

        if (lane == 0 && wmask != MASK_ALL) atomicAnd(&s_mask, wmask);
        __syncthreads();

        if (tid == 0) atomicAnd(&g_and[k], s_mask);

        GRID_BARRIER();   // all masks for iteration k combined

        if (tid == 0) {
            const unsigned tt = *(volatile unsigned*)&g_and[k] & MASK_ALL;
            float st = 0.f;
            if (tt) st = ldexpf(1.f, -(__ffs(tt) - 1));
            s_step = st;
        }
        __syncthreads();

        // x and Ax updated by their owner threads (no extra sync needed:
        // next iteration's v-block reads s_Ax[tid] written by the same tid,
        // and the grad block reads s_x[tid] written by the same tid).
        if (tid < NDIM) s_x[tid] = fmaf(-s_step, s_grad[tid], s_x[tid]);
        if (tid < MDIM) s_Ax[tid] = fmaf(-s_step, s_Ag[tid], s_Ax[tid]);
    }

    // finalize: relu(x) -> out
    if (tid < NDIM) out[p * NDIM + tid] = fmaxf(s_x[tid], 0.f);
}

extern "C" void kernel_launch(void* const* d_in, const int* in_sizes, int n_in,
                              void* d_out, int out_size) {
    // Identify inputs by size (dict order: x_raw, A, b, lower).
    int iA = 1, ib = 2, iv1 = 0, iv2 = 3;
    {
        int big = -1, small = -1, v1 = -1, v2 = -1;
        for (int i = 0; i < n_in; i++) {
            if (in_sizes[i] == NPROB * MDIM * NDIM) big = i;
            else if (in_sizes[i] == NPROB * MDIM)   small = i;
            else if (v1 < 0) v1 = i;
            else             v2 = i;
        }
        if (big >= 0 && small >= 0 && v1 >= 0 && v2 >= 0) {
            iA = big; ib = small; iv1 = v1; iv2 = v2;
        }
    }
    const float* xr  = (const float*)d_in[iv1];
    const float* A   = (const float*)d_in[iA];
    const float* b   = (const float*)d_in[ib];
    const float* low = (const float*)d_in[iv2];
    float* out = (float*)d_out;

    // Opt-in: static (~14.4KB) + dynamic (40KB) > 48KB default per-block limit.
    // Not a stream-ordered call -> does not enter / invalidate graph capture.
    cudaFuncSetAttribute(persist_kernel,
                         cudaFuncAttributeMaxDynamicSharedMemorySize, DYNSMEM);

    persist_kernel<<<NPROB, TPB, DYNSMEM>>>(xr, A, b, low, out);
}

// round 9
// speedup vs baseline: 1.7818x; 1.0240x over previous
#include <cuda_runtime.h>
#include <cstdint>

#define NPROB 512            // B*S = 32*16
#define MDIM  128
#define NDIM  256
#define EPSF  1e-6f
#define MUF   0.01f
#define KITER 30
#define LMAX  25
#define MASK_ALL 0x01FFFFFFu // 25 bits
#define TPB   256
#define CJ    5              // cached row-groups per warp (rows 0..39 in smem)
#define CROWS (CJ * 8)       // 40 rows cached
#define DYNSMEM (CROWS * NDIM * 4)

typedef unsigned long long u64;

// Persistent device state
__device__ float    g_Aw[(size_t)NPROB * MDIM * NDIM]; // row-normalized A (64MB)
__device__ unsigned g_and[KITER];                       // global AND of masks per iter
__device__ unsigned g_count;                            // barrier arrival counter
__device__ unsigned g_sense;                            // barrier sense

// ---- packed f32x2 helpers (sm_103a FFMA2 path; per-element IEEE fp32) ----
__device__ __forceinline__ u64 pack2(float x, float y) {
    u64 r; asm("mov.b64 %0, {%1, %2};" : "=l"(r) : "f"(x), "f"(y)); return r;
}
__device__ __forceinline__ void unpack2(u64 v, float& x, float& y) {
    asm("mov.b64 {%0, %1}, %2;" : "=f"(x), "=f"(y) : "l"(v));
}
__device__ __forceinline__ u64 fma2(u64 a, u64 b, u64 c) {
    u64 d; asm("fma.rn.f32x2 %0, %1, %2, %3;" : "=l"(d) : "l"(a), "l"(b), "l"(c));
    return d;
}
__device__ __forceinline__ u64 mul2(u64 a, u64 b) {
    u64 d; asm("mul.rn.f32x2 %0, %1, %2;" : "=l"(d) : "l"(a), "l"(b));
    return d;
}

// NOTE: redux.sync.add.f32 is NOT supported on sm_103 (ptxas rejects it).
__device__ __forceinline__ float warp_allreduce_add(float v) {
#pragma unroll
    for (int o = 16; o; o >>= 1) v += __shfl_xor_sync(0xffffffffu, v, o);
    return v;
}

__device__ __forceinline__ float dot8(float4 a0, float4 a1, float4 b0, float4 b1) {
    float s = a0.x * b0.x + a0.y * b0.y + a0.z * b0.z + a0.w * b0.w;
    s += a1.x * b1.x + a1.y * b1.y + a1.z * b1.z + a1.w * b1.w;
    return s;
}

// Grid-wide sense-reversal barrier. All NPROB CTAs co-resident:
// __launch_bounds__(256,4) + ~55KB smem/CTA -> 4 CTAs/SM * 148 = 592 >= 512.
#define GRID_BARRIER()                                                        \
    do {                                                                      \
        __syncthreads();                                                      \
        if (tid == 0) {                                                       \
            const unsigned target = sense ^ 1u;                               \
            __threadfence();                                                  \
            if (atomicAdd(&g_count, 1u) == NPROB - 1u) {                      \
                atomicExch(&g_count, 0u);                                     \
                __threadfence();                                              \
                atomicExch(&g_sense, target);                                 \
            } else {                                                          \
                while (*(volatile unsigned*)&g_sense != target)               \
                    __nanosleep(64);                                          \
            }                                                                 \
            sense = target;                                                   \
            __threadfence();                                                  \
        }                                                                     \
        __syncthreads();                                                      \
    } while (0)

__global__ void __launch_bounds__(TPB, 4)
persist_kernel(const float* __restrict__ xraw,
               const float* __restrict__ Ain,
               const float* __restrict__ bin,
               const float* __restrict__ lowin,
               float* __restrict__ out)
{
    extern __shared__ __align__(16) float sA[];   // CROWS x NDIM pinned A rows

    const int p    = blockIdx.x;
    const int tid  = threadIdx.x;
    const int lane = tid & 31;
    const int w    = tid >> 5;

    __shared__ __align__(16) float s_x[NDIM];
    __shared__ __align__(16) float s_grad[NDIM];
    __shared__ __align__(16) float s_lo[NDIM];
    __shared__ __align__(16) float s_xr[NDIM];
    __shared__ __align__(16) float s_bw[MDIM];
    __shared__ __align__(16) float s_Ax[MDIM];
    __shared__ __align__(16) float s_Ag[MDIM];
    __shared__ __align__(16) float s_v[MDIM];
    __shared__ __align__(16) float s_gb[8 * NDIM];   // per-warp gbar partials
    __shared__ unsigned s_mask;
    __shared__ float    s_step;
    __shared__ int      s_feas;

    const float* A  = Ain  + (size_t)p * MDIM * NDIM;
    float*       Aw = g_Aw + (size_t)p * MDIM * NDIM;

    // Read sense BEFORE first arrive (all CTAs read pre-flip value).
    unsigned sense = *(volatile unsigned*)&g_sense;

    if (p == 0 && tid < KITER) g_and[tid] = MASK_ALL;

    if (tid < NDIM) {
        s_lo[tid] = lowin[p * NDIM + tid];
        s_xr[tid] = xraw[p * NDIM + tid];
    }
    if (tid == 0) s_feas = 1;
    __syncthreads();

    const int n0 = 4 * lane;
    const int n1 = 128 + 4 * lane;
    const float4 l0 = *(const float4*)(s_lo + n0);
    const float4 l1 = *(const float4*)(s_lo + n1);

    // per-lane line-search step: lane l tests step 2^-l (exact power of two)
    const float stepl = __uint_as_float((unsigned)(127 - lane) << 23);

    float* s_red = s_gb;   // alias: s_gb unused during setup

    // ---------------- setup: row-normalize, cache first 40 rows in smem -----
#pragma unroll 4
    for (int j = 0; j < 16; j++) {
        const int m = w + 8 * j;
        const float4 a0 = *(const float4*)(A + (size_t)m * NDIM + n0);
        const float4 a1 = *(const float4*)(A + (size_t)m * NDIM + n1);
        float ss = warp_allreduce_add(dot8(a0, a1, a0, a1));
        const float norm = fmaxf(sqrtf(ss), 1e-12f);
        float4 w0, w1;
        w0.x = a0.x / norm; w0.y = a0.y / norm; w0.z = a0.z / norm; w0.w = a0.w / norm;
        w1.x = a1.x / norm; w1.y = a1.y / norm; w1.z = a1.z / norm; w1.w = a1.w / norm;
        *(float4*)(Aw + (size_t)m * NDIM + n0) = w0;
        *(float4*)(Aw + (size_t)m * NDIM + n1) = w1;
        if (m < CROWS) {
            *(float4*)(sA + m * NDIM + n0) = w0;
            *(float4*)(sA + m * NDIM + n1) = w1;
        }
        float ad = (w0.x + w0.y + w0.z + w0.w) + (w1.x + w1.y + w1.z + w1.w);
        float sd = dot8(w0, w1, l0, l1);
        ad = warp_allreduce_add(ad);
        sd = warp_allreduce_add(sd);
        if (lane == 0) {
            const float bwm = bin[p * MDIM + m] / norm;
            s_bw[m]  = bwm;
            s_Ax[m]  = ad;          // temp: Ad
            s_red[m] = bwm - sd;    // temp: slack at lower
        }
    }
    __syncthreads();

    // t = max(0.5 * min_m ratio, 2*eps)
    if (tid < MDIM) {
        const float ad = s_Ax[tid];
        s_red[tid] = (ad > 0.f) ? (s_red[tid] / fmaxf(ad, 1e-12f))
                                : __int_as_float(0x7f800000); // +inf
    }
    __syncthreads();
    for (int off = 64; off >= 1; off >>= 1) {
        if (tid < off) s_red[tid] = fminf(s_red[tid], s_red[tid + off]);
        __syncthreads();
    }
    const float t = fmaxf(0.5f * s_red[0], 2.f * EPSF);
    __syncthreads();   // s_red (=s_gb) free again

    // feasibility of x = lower + t (fresh dots); also seeds s_Ax = A*x
    {
        float4 xq0, xq1;
        xq0.x = l0.x + t; xq0.y = l0.y + t; xq0.z = l0.z + t; xq0.w = l0.w + t;
        xq1.x = l1.x + t; xq1.y = l1.y + t; xq1.z = l1.z + t; xq1.w = l1.w + t;
#pragma unroll
        for (int j = 0; j < CJ; j++) {
            const int m = w + 8 * j;
            const float4 a0 = *(const float4*)(sA + m * NDIM + n0);
            const float4 a1 = *(const float4*)(sA + m * NDIM + n1);
            float d = warp_allreduce_add(dot8(a0, a1, xq0, xq1));
            if (lane == 0) {
                s_Ax[m] = d;
                if (!(d <= s_bw[m] - EPSF)) atomicAnd(&s_feas, 0);
            }
        }
#pragma unroll 4
        for (int j = CJ; j < 16; j++) {
            const int m = w + 8 * j;
            const float4 a0 = *(const float4*)(Aw + (size_t)m * NDIM + n0);
            const float4 a1 = *(const float4*)(Aw + (size_t)m * NDIM + n1);
            float d = warp_allreduce_add(dot8(a0, a1, xq0, xq1));
            if (lane == 0) {
                s_Ax[m] = d;
                if (!(d <= s_bw[m] - EPSF)) atomicAnd(&s_feas, 0);
            }
        }
        if (tid < NDIM) {
            const float xv = s_lo[tid] + t;
            if (!(xv >= s_lo[tid] + EPSF)) atomicAnd(&s_feas, 0);
        }
        __syncthreads();
        if (tid < NDIM) {
            float xv = s_lo[tid] + t;
            if (!s_feas) xv = 0.5f * (fmaxf(xv, 0.f) + s_lo[tid]);
            s_x[tid] = xv;
        }
        __syncthreads();
        if (!s_feas) {   // rare repair branch: recompute Ax of repaired x
            const float4 r0 = *(const float4*)(s_x + n0);
            const float4 r1 = *(const float4*)(s_x + n1);
            for (int j = 0; j < 16; j++) {
                const int m = w + 8 * j;
                const float* src = (j < CJ) ? (sA + m * NDIM)
                                            : (Aw + (size_t)m * NDIM);
                const float4 a0 = *(const float4*)(src + n0);
                const float4 a1 = *(const float4*)(src + n1);
                float d = warp_allreduce_add(dot8(a0, a1, r0, r1));
                if (lane == 0) s_Ax[m] = d;
            }
        }
    }

    GRID_BARRIER();   // barrier #0: g_and init + everyone's setup done

    // ---------------- main loop (incremental Ax: Ax_{k+1} = Ax_k - step*Ag) --
    for (int k = 0; k < KITER; k++) {
        if (tid == 0) s_mask = MASK_ALL;
        // v[m] = mu / max(bw - Ax, 1e-12) -- Ax maintained incrementally
        if (tid < MDIM)
            s_v[tid] = __fdividef(MUF, fmaxf(s_bw[tid] - s_Ax[tid], 1e-12f));
        __syncthreads();

        // ---- pass G: gbar partials (pure streaming, no reduce/div) ---------
        u64 ga0 = 0ull, ga1 = 0ull, ga2 = 0ull, ga3 = 0ull;

#define PG_ROW(A0, A1, m)                                                     \
        do {                                                                  \
            const float v_ = s_v[m];                                          \
            const u64 vv = pack2(v_, v_);                                     \
            ga0 = fma2((A0).x, vv, ga0); ga1 = fma2((A0).y, vv, ga1);         \
            ga2 = fma2((A1).x, vv, ga2); ga3 = fma2((A1).y, vv, ga3);         \
        } while (0)

        // gmem rows ascending (j=CJ..15), deep unroll for MLP
#pragma unroll 8
        for (int j = CJ; j < 16; j++) {
            const int m = w + 8 * j;
            const ulonglong2 a0 = *(const ulonglong2*)(Aw + (size_t)m * NDIM + n0);
            const ulonglong2 a1 = *(const ulonglong2*)(Aw + (size_t)m * NDIM + n1);
            PG_ROW(a0, a1, m);
        }
        // smem-pinned rows
#pragma unroll
        for (int j = 0; j < CJ; j++) {
            const int m = w + 8 * j;
            const ulonglong2 a0 = *(const ulonglong2*)(sA + m * NDIM + n0);
            const ulonglong2 a1 = *(const ulonglong2*)(sA + m * NDIM + n1);
            PG_ROW(a0, a1, m);
        }
#undef PG_ROW

        {
            ulonglong2 t0; t0.x = ga0; t0.y = ga1;
            ulonglong2 t1; t1.x = ga2; t1.y = ga3;
            *(ulonglong2*)(s_gb + w * NDIM + n0) = t0;
            *(ulonglong2*)(s_gb + w * NDIM + n1) = t1;
        }
        __syncthreads();

        // grad + column-constraint mask bits (per-thread, serial + fast path)
        if (tid < NDIM) {
            float gb = 0.f;
#pragma unroll
            for (int j = 0; j < 8; j++) gb += s_gb[j * NDIM + tid];
            const float xv  = s_x[tid];
            const float lov = s_lo[tid];
            const float slo = fmaxf(xv - lov, 1e-12f);
            const float gr  = (xv - s_xr[tid]) + gb + __fdividef(MUF, slo);
            s_grad[tid] = gr;

            const float lim = lov + EPSF;
            if (!(gr <= 0.f && xv >= lim)) {   // fast path: all candidates pass
                unsigned mk = MASK_ALL;
                float st = 1.f;
#pragma unroll
                for (int l = 0; l < LMAX; l++) {
                    const float c = fmaf(-st, gr, xv);
                    if (!(c >= lim)) mk &= ~(1u << l);
                    st *= 0.5f;
                }
                if (mk != MASK_ALL) atomicAnd(&s_mask, mk);
            }
        }
        __syncthreads();

        // ---- pass A: Ag dots + row masks via lane-parallel ballot ----------
        // lane l tests candidate step 2^-l -> bit l (bit-identical fmaf).
        const ulonglong2 gA = *(const ulonglong2*)(s_grad + n0);
        const ulonglong2 gB = *(const ulonglong2*)(s_grad + n1);
        unsigned wmask = MASK_ALL;

#define PA_ROW(A0, A1, m)                                                     \
        do {                                                                  \
            u64 s = mul2((A0).x, gA.x);                                       \
            s = fma2((A0).y, gA.y, s);                                        \
            s = fma2((A1).x, gB.x, s);                                        \
            s = fma2((A1).y, gB.y, s);                                        \
            float slo_, shi_; unpack2(s, slo_, shi_);                         \
            float ag = warp_allreduce_add(slo_ + shi_);                       \
            if (lane == 0) s_Ag[m] = ag;                                      \
            const float axc = fmaf(-stepl, ag, s_Ax[m]);                      \
            const unsigned bits =                                             \
                __ballot_sync(0xffffffffu, axc <= s_bw[m] - EPSF);            \
            wmask &= (bits | ~MASK_ALL);                                      \
        } while (0)

        // gmem rows DESCENDING (j=15..CJ): j=15 just read by pass G -> L2 hot
#pragma unroll 8
        for (int j = 15; j >= CJ; j--) {
            const int m = w + 8 * j;
            const ulonglong2 a0 = *(const ulonglong2*)(Aw + (size_t)m * NDIM + n0);
            const ulonglong2 a1 = *(const ulonglong2*)(Aw + (size_t)m * NDIM + n1);
            PA_ROW(a0, a1, m);
        }
        // smem-pinned rows
#pragma unroll
        for (int j = 0; j < CJ; j++) {
            const int m = w + 8 * j;
            const ulonglong2 a0 = *(const ulonglong2*)(sA + m * NDIM + n0);
            const ulonglong2 a1 = *(const ulonglong2*)(sA + m * NDIM + n1);
            PA_ROW(a0, a1, m);
        }
#undef PA_ROW

        if (lane == 0 && wmask != MASK_ALL) atomicAnd(&s_mask, wmask);
        __syncthreads();

        if (tid == 0) atomicAnd(&g_and[k], s_mask);

        GRID_BARRIER();   // all masks for iteration k combined

        if (tid == 0) {
            const unsigned tt = *(volatile unsigned*)&g_and[k] & MASK_ALL;
            float st = 0.f;
            if (tt) st = ldexpf(1.f, -(__ffs(tt) - 1));
            s_step = st;
        }
        __syncthreads();

        // owner-thread updates (same tid reads its own write next iteration)
        if (tid < NDIM) s_x[tid] = fmaf(-s_step, s_grad[tid], s_x[tid]);
        if (tid < MDIM) s_Ax[tid] = fmaf(-s_step, s_Ag[tid], s_Ax[tid]);
    }

    // finalize: relu(x) -> out
    if (tid < NDIM) out[p * NDIM + tid] = fmaxf(s_x[tid], 0.f);
}

extern "C" void kernel_launch(void* const* d_in, const int* in_sizes, int n_in,
                              void* d_out, int out_size) {
    // Identify inputs by size (dict order: x_raw, A, b, lower).
    int iA = 1, ib = 2, iv1 = 0, iv2 = 3;
    {
        int big = -1, small = -1, v1 = -1, v2 = -1;
        for (int i = 0; i < n_in; i++) {
            if (in_sizes[i] == NPROB * MDIM * NDIM) big = i;
            else if (in_sizes[i] == NPROB * MDIM)   small = i;
            else if (v1 < 0) v1 = i;
            else             v2 = i;
        }
        if (big >= 0 && small >= 0 && v1 >= 0 && v2 >= 0) {
            iA = big; ib = small; iv1 = v1; iv2 = v2;
        }
    }
    const float* xr  = (const float*)d_in[iv1];
    const float* A   = (const float*)d_in[iA];
    const float* b   = (const float*)d_in[ib];
    const float* low = (const float*)d_in[iv2];
    float* out = (float*)d_out;

    // Opt-in: static (~14.9KB) + dynamic (40KB) > 48KB default per-block limit.
    // Not a stream-ordered call -> does not enter / invalidate graph capture.
    cudaFuncSetAttribute(persist_kernel,
                         cudaFuncAttributeMaxDynamicSharedMemorySize, DYNSMEM);

    persist_kernel<<<NPROB, TPB, DYNSMEM>>>(xr, A, b, low, out);
}